// round 9
// baseline (speedup 1.0000x reference)
#include <cuda_runtime.h>
#include <cuda_fp16.h>
#include <cstdint>

#define BATCH 4
#define SEQ   2048
#define DM    1024
#define NH    16
#define DK    64
#define MTOT  (BATCH*SEQ)   // 8192

// ---------------- device scratch (allocation-free) ----------------
__device__ __half g_X16[MTOT*DM];
__device__ __half g_Q16[MTOT*DM], g_K16[MTOT*DM], g_V16[MTOT*DM];
__device__ __half g_C16[MTOT*DM];
__device__ __half g_Wq16[DM*DM], g_Wk16[DM*DM], g_Wv16[DM*DM], g_Wo16[DM*DM];

// ---------------- PTX helpers --------------------------------------------
__device__ __forceinline__ uint32_t smem_u32(const void* p) {
    uint32_t a;
    asm("{ .reg .u64 t; cvta.to.shared.u64 t, %1; cvt.u32.u64 %0, t; }" : "=r"(a) : "l"(p));
    return a;
}
__device__ __forceinline__ void cp16(uint32_t s, const void* g) {
    asm volatile("cp.async.cg.shared.global [%0], [%1], 16;" :: "r"(s), "l"(g));
}
__device__ __forceinline__ void cp_commit() {
    asm volatile("cp.async.commit_group;" ::: "memory");
}
template<int N> __device__ __forceinline__ void cp_wait() {
    asm volatile("cp.async.wait_group %0;" :: "n"(N) : "memory");
}
__device__ __forceinline__ void ldsm4(uint32_t& r0, uint32_t& r1, uint32_t& r2, uint32_t& r3,
                                      uint32_t addr) {
    asm volatile("ldmatrix.sync.aligned.m8n8.x4.shared.b16 {%0,%1,%2,%3}, [%4];"
                 : "=r"(r0), "=r"(r1), "=r"(r2), "=r"(r3) : "r"(addr));
}
__device__ __forceinline__ void ldsm4t(uint32_t& r0, uint32_t& r1, uint32_t& r2, uint32_t& r3,
                                       uint32_t addr) {
    asm volatile("ldmatrix.sync.aligned.m8n8.x4.trans.shared.b16 {%0,%1,%2,%3}, [%4];"
                 : "=r"(r0), "=r"(r1), "=r"(r2), "=r"(r3) : "r"(addr));
}
__device__ __forceinline__ void mma16816h(float* c, const uint32_t* a, const uint32_t* b) {
    asm volatile(
        "mma.sync.aligned.m16n8k16.row.col.f32.f16.f16.f32 "
        "{%0,%1,%2,%3}, {%4,%5,%6,%7}, {%8,%9}, {%0,%1,%2,%3};"
        : "+f"(c[0]), "+f"(c[1]), "+f"(c[2]), "+f"(c[3])
        : "r"(a[0]), "r"(a[1]), "r"(a[2]), "r"(a[3]), "r"(b[0]), "r"(b[1]));
}
__device__ __forceinline__ float ex2f(float x) {
    float y;
    asm("ex2.approx.ftz.f32 %0, %1;" : "=f"(y) : "f"(x));
    return y;
}
__device__ __forceinline__ uint32_t packf2h(float x, float y) {
    __half2 t = __floats2half2_rn(x, y);
    return *reinterpret_cast<uint32_t*>(&t);
}

// ---------------------------------------------------------------------------
// fp32 -> fp16 converters
// ---------------------------------------------------------------------------
__global__ void cvt_kernel(const float* __restrict__ in, __half* __restrict__ out, int n4)
{
    int i = blockIdx.x * blockDim.x + threadIdx.x;
    if (i >= n4) return;
    float4 v = ((const float4*)in)[i];
    uint32_t* op = reinterpret_cast<uint32_t*>(out) + 2 * i;
    op[0] = packf2h(v.x, v.y);
    op[1] = packf2h(v.z, v.w);
}
__global__ void cvt4_kernel(const float* __restrict__ a, const float* __restrict__ b,
                            const float* __restrict__ c, const float* __restrict__ d,
                            __half* oa, __half* ob, __half* oc, __half* od, int n4)
{
    int i = blockIdx.x * blockDim.x + threadIdx.x;
    if (i >= n4) return;
    const float* in = (blockIdx.y == 0) ? a : (blockIdx.y == 1) ? b : (blockIdx.y == 2) ? c : d;
    __half*     out = (blockIdx.y == 0) ? oa : (blockIdx.y == 1) ? ob : (blockIdx.y == 2) ? oc : od;
    float4 v = ((const float4*)in)[i];
    uint32_t* op = reinterpret_cast<uint32_t*>(out) + 2 * i;
    op[0] = packf2h(v.x, v.y);
    op[1] = packf2h(v.z, v.w);
}

// ---------------------------------------------------------------------------
// 1-pass fp16 GEMM:  C[8192,1024] = A @ W^T + bias  (optionally *scale)
// CTA 128x128, 128 threads = 4 warps, warp tile 64x64. KC=32 double-buffered.
// ---------------------------------------------------------------------------
#define KC        32
#define CHUNKS    (DM / KC)       // 32
#define ROWB      80              // smem bytes per 32-half row (+16B pad)
#define BUFB      (128 * ROWB)    // 10240
#define STGB      (2 * BUFB)      // 20480: A, B
#define GEMM_SMEM (2 * STGB)      // 40960

// EPI: 0 = fp32 out, 1 = fp16 out with scale
template<int EPI>
__device__ __forceinline__ void gemm_body(
    const __half* __restrict__ A_, const __half* __restrict__ B_,
    const float* __restrict__ bias, float scale,
    float* __restrict__ C, __half* __restrict__ Ch, char* smem)
{
    const uint32_t sbase = smem_u32(smem);
    const int tid = threadIdx.x, wid = tid >> 5, lane = tid & 31;
    const int bm = blockIdx.y * 128, bn = blockIdx.x * 128;
    const int wm = (wid & 1) * 64;     // warp m offset
    const int wn = (wid >> 1) * 64;    // warp n offset

    const char* pA = (const char*)(A_ + (size_t)bm * DM);
    const char* pB = (const char*)(B_ + (size_t)bn * DM);

    int so_[4]; size_t go_[4];
    #pragma unroll
    for (int j = 0; j < 4; j++) {
        int idx = j * 128 + tid;          // 0..511
        int row = idx >> 2, c16 = (idx & 3) * 16;
        so_[j] = row * ROWB + c16;
        go_[j] = (size_t)row * (DM * 2) + c16;
    }

    auto load_chunk = [&](int c) {
        uint32_t sb = sbase + (uint32_t)(c & 1) * STGB;
        size_t kb = (size_t)c * (KC * 2);
        #pragma unroll
        for (int j = 0; j < 4; j++) {
            size_t g = go_[j] + kb;
            cp16(sb + so_[j],        pA + g);
            cp16(sb + BUFB + so_[j], pB + g);
        }
        cp_commit();
    };

    float acc[4][8][4];
    #pragma unroll
    for (int mt = 0; mt < 4; mt++)
        #pragma unroll
        for (int nt = 0; nt < 8; nt++)
            #pragma unroll
            for (int e = 0; e < 4; e++) acc[mt][nt][e] = 0.0f;

    const int aRow = wm + (lane & 15);
    const int aKo  = (lane >> 4) * 16;
    const int bRow = wn + ((lane >> 4) & 1) * 8 + (lane & 7);
    const int bKo  = ((lane >> 3) & 1) * 16;

    load_chunk(0);
    load_chunk(1);

    for (int i = 0; i < CHUNKS; i++) {
        if (i == CHUNKS - 1) cp_wait<0>(); else cp_wait<1>();
        __syncthreads();

        const uint32_t sb = sbase + (uint32_t)(i & 1) * STGB;
        const uint32_t aB = sb, bB = sb + BUFB;

        #pragma unroll
        for (int ks = 0; ks < 2; ks++) {
            const int ko = ks * 32;
            uint32_t ah[4][4], bh[8][2];
            #pragma unroll
            for (int mt = 0; mt < 4; mt++)
                ldsm4(ah[mt][0], ah[mt][1], ah[mt][2], ah[mt][3],
                      aB + (uint32_t)((aRow + mt * 16) * ROWB + ko + aKo));
            #pragma unroll
            for (int np = 0; np < 4; np++)
                ldsm4(bh[2*np][0], bh[2*np][1], bh[2*np+1][0], bh[2*np+1][1],
                      bB + (uint32_t)((bRow + np * 16) * ROWB + ko + bKo));
            #pragma unroll
            for (int mt = 0; mt < 4; mt++)
                #pragma unroll
                for (int nt = 0; nt < 8; nt++)
                    mma16816h(acc[mt][nt], ah[mt], bh[nt]);
        }
        __syncthreads();
        if (i + 2 < CHUNKS) load_chunk(i + 2);
    }

    const int g  = lane >> 2, tg = lane & 3;
    #pragma unroll
    for (int mt = 0; mt < 4; mt++) {
        const int r0 = bm + wm + mt * 16 + g;
        #pragma unroll
        for (int nt = 0; nt < 8; nt++) {
            const int col = bn + wn + nt * 8 + tg * 2;
            const float b0 = bias[col], b1 = bias[col + 1];
            float v00 = acc[mt][nt][0] + b0, v01 = acc[mt][nt][1] + b1;
            float v10 = acc[mt][nt][2] + b0, v11 = acc[mt][nt][3] + b1;
            if (EPI == 0) {
                *(float2*)&C[(size_t)r0 * DM + col]       = make_float2(v00, v01);
                *(float2*)&C[(size_t)(r0 + 8) * DM + col] = make_float2(v10, v11);
            } else {
                *(uint32_t*)&Ch[(size_t)r0 * DM + col]       = packf2h(v00 * scale, v01 * scale);
                *(uint32_t*)&Ch[(size_t)(r0 + 8) * DM + col] = packf2h(v10 * scale, v11 * scale);
            }
        }
    }
}

#define SC2F (0.125f * 1.44269504088896f)   // 1/sqrt(dk) * log2(e)

__global__ __launch_bounds__(128)
void gemm_qkv(const __half* __restrict__ X16,
              const __half* __restrict__ Wq, const __half* __restrict__ Wk,
              const __half* __restrict__ Wv,
              const float* __restrict__ bq, const float* __restrict__ bk,
              const float* __restrict__ bv,
              __half* __restrict__ Q, __half* __restrict__ K, __half* __restrict__ V)
{
    extern __shared__ char smem[];
    const int z = blockIdx.z;
    const __half* W   = (z == 0) ? Wq : (z == 1) ? Wk : Wv;
    const float* bias = (z == 0) ? bq : (z == 1) ? bk : bv;
    __half* O         = (z == 0) ? Q  : (z == 1) ? K  : V;
    const float scale = (z == 0) ? SC2F : 1.0f;
    gemm_body<1>(X16, W, bias, scale, nullptr, O, smem);
}

__global__ __launch_bounds__(128)
void gemm_o(const __half* __restrict__ C16, const __half* __restrict__ Wo,
            const float* __restrict__ bo, float* __restrict__ out)
{
    extern __shared__ char smem[];
    gemm_body<0>(C16, Wo, bo, 1.0f, out, nullptr, smem);
}

// ---------------------------------------------------------------------------
// Tensor-core flash attention, fp16, static softmax.
// CTA = 128 q rows, 4 warps, each warp m=32 (2 m-tiles) -> 2 CTAs/SM.
// KV tile 64 processed in two n=32 halves to bound live registers.
// ---------------------------------------------------------------------------
#define ABQ    128
#define ATHR   128
#define ABKV   64
#define AROWB  144                 // 64 halves = 128B + 16B pad
#define AQSZ   (ABQ * AROWB)       // 18432
#define AKSZ   (ABKV * AROWB)      // 9216
#define ASTG   (2 * AKSZ)          // 18432: K, V
#define AKOFF  AQSZ
#define ATT_SMEM (AKOFF + 2 * ASTG)  // 55296
#define NKV    (SEQ / ABKV)        // 32

__global__ __launch_bounds__(ATHR, 2)
void attn_mma(const __half* __restrict__ Qg, const __half* __restrict__ Kg,
              const __half* __restrict__ Vg, __half* __restrict__ Ch)
{
    extern __shared__ char smem[];
    const uint32_t sbase = smem_u32(smem);
    const int b   = blockIdx.z;
    const int h   = blockIdx.y;
    const int q0  = blockIdx.x * ABQ;
    const int tid = threadIdx.x, wid = tid >> 5, lane = tid & 31;

    const size_t hoff = ((size_t)b * SEQ) * DM + (size_t)h * DK;
    const char* gQ = (const char*)(Qg + hoff + (size_t)q0 * DM);
    const char* gK = (const char*)(Kg + hoff);
    const char* gV = (const char*)(Vg + hoff);

    // ---- load Q tile (128 rows x 128B) ----
    #pragma unroll
    for (int j = 0; j < 8; j++) {
        int idx = tid + j * ATHR;         // 0..1023
        int row = idx >> 3, seg = (idx & 7) * 16;
        cp16(sbase + (uint32_t)(row * AROWB + seg), gQ + (size_t)row * (DM * 2) + seg);
    }
    cp_commit();

    // ---- kv tile loader ----
    int so_[4]; size_t go_[4];
    #pragma unroll
    for (int j = 0; j < 4; j++) {
        int idx = tid + j * ATHR;         // 0..511
        int row = idx >> 3, seg = (idx & 7) * 16;
        so_[j] = row * AROWB + seg;
        go_[j] = (size_t)row * (DM * 2) + seg;
    }
    auto load_kv = [&](int it) {
        uint32_t sb = sbase + AKOFF + (uint32_t)(it & 1) * ASTG;
        size_t kvb = (size_t)it * ABKV * (DM * 2);
        #pragma unroll
        for (int j = 0; j < 4; j++) {
            size_t g = go_[j] + kvb;
            cp16(sb + so_[j],        gK + g);
            cp16(sb + AKSZ + so_[j], gV + g);
        }
        cp_commit();
    };
    load_kv(0);
    load_kv(1);

    // ---- Q fragments to registers: 2 m-tiles x 4 k-blocks ----
    cp_wait<2>();
    __syncthreads();
    uint32_t qh[2][4][4];
    {
        const int qko = (lane >> 4) * 16;
        #pragma unroll
        for (int mt = 0; mt < 2; mt++) {
            const int qrow = wid * 32 + mt * 16 + (lane & 15);
            #pragma unroll
            for (int j = 0; j < 4; j++)
                ldsm4(qh[mt][j][0], qh[mt][j][1], qh[mt][j][2], qh[mt][j][3],
                      sbase + (uint32_t)(qrow * AROWB + j * 32 + qko));
        }
    }

    float o[2][8][4];
    #pragma unroll
    for (int mt = 0; mt < 2; mt++)
        #pragma unroll
        for (int nt = 0; nt < 8; nt++)
            #pragma unroll
            for (int e = 0; e < 4; e++) o[mt][nt][e] = 0.0f;
    float lsum[2][2] = {{0.0f, 0.0f}, {0.0f, 0.0f}};

    const int kRow = ((lane >> 4) & 1) * 8 + (lane & 7);
    const int kKo  = ((lane >> 3) & 1) * 16;
    const int vRow = ((lane >> 3) & 1) * 8 + (lane & 7);
    const int vCo  = ((lane >> 4) & 1) * 16;

    for (int it = 0; it < NKV; it++) {
        if (it == NKV - 1) cp_wait<0>(); else cp_wait<1>();
        __syncthreads();
        const uint32_t sb = sbase + AKOFF + (uint32_t)(it & 1) * ASTG;

        #pragma unroll
        for (int half = 0; half < 2; half++) {
            const int hbase = half * 32;

            // ---- S(half) = Q(m32,k64) . K[n32]^T ----
            float s[2][4][4];
            #pragma unroll
            for (int mt = 0; mt < 2; mt++)
                #pragma unroll
                for (int nt = 0; nt < 4; nt++)
                    #pragma unroll
                    for (int e = 0; e < 4; e++) s[mt][nt][e] = 0.0f;
            #pragma unroll
            for (int j = 0; j < 4; j++) {
                uint32_t kf[4][2];
                #pragma unroll
                for (int np = 0; np < 2; np++)
                    ldsm4(kf[2*np][0], kf[2*np][1], kf[2*np+1][0], kf[2*np+1][1],
                          sb + (uint32_t)((hbase + np * 16 + kRow) * AROWB + j * 32 + kKo));
                #pragma unroll
                for (int mt = 0; mt < 2; mt++)
                    #pragma unroll
                    for (int nt = 0; nt < 4; nt++)
                        mma16816h(s[mt][nt], qh[mt][j], kf[nt]);
            }

            // ---- static softmax: P = exp2(s); pack A-frags; accumulate l ----
            uint32_t ph[2][2][4];
            #pragma unroll
            for (int mt = 0; mt < 2; mt++) {
                #pragma unroll
                for (int ks = 0; ks < 2; ks++) {
                    const int t0 = 2 * ks, t1 = 2 * ks + 1;
                    float p00 = ex2f(s[mt][t0][0]), p01 = ex2f(s[mt][t0][1]);
                    float p02 = ex2f(s[mt][t0][2]), p03 = ex2f(s[mt][t0][3]);
                    float p10 = ex2f(s[mt][t1][0]), p11 = ex2f(s[mt][t1][1]);
                    float p12 = ex2f(s[mt][t1][2]), p13 = ex2f(s[mt][t1][3]);
                    lsum[mt][0] += (p00 + p01) + (p10 + p11);
                    lsum[mt][1] += (p02 + p03) + (p12 + p13);
                    ph[mt][ks][0] = packf2h(p00, p01);
                    ph[mt][ks][1] = packf2h(p02, p03);
                    ph[mt][ks][2] = packf2h(p10, p11);
                    ph[mt][ks][3] = packf2h(p12, p13);
                }
            }

            // ---- O += P(half) . V[half rows] ----
            #pragma unroll
            for (int ks = 0; ks < 2; ks++) {
                uint32_t vf[8][2];
                #pragma unroll
                for (int np = 0; np < 4; np++)
                    ldsm4t(vf[2*np][0], vf[2*np][1], vf[2*np+1][0], vf[2*np+1][1],
                           sb + AKSZ + (uint32_t)((hbase + ks * 16 + vRow) * AROWB + np * 32 + vCo));
                #pragma unroll
                for (int mt = 0; mt < 2; mt++)
                    #pragma unroll
                    for (int nt = 0; nt < 8; nt++)
                        mma16816h(o[mt][nt], ph[mt][ks], vf[nt]);
            }
        }

        __syncthreads();
        if (it + 2 < NKV) load_kv(it + 2);
    }

    // ---- l reduction (4-lane row groups), normalize, store ----
    #pragma unroll
    for (int mt = 0; mt < 2; mt++) {
        lsum[mt][0] += __shfl_xor_sync(0xffffffffu, lsum[mt][0], 1);
        lsum[mt][0] += __shfl_xor_sync(0xffffffffu, lsum[mt][0], 2);
        lsum[mt][1] += __shfl_xor_sync(0xffffffffu, lsum[mt][1], 1);
        lsum[mt][1] += __shfl_xor_sync(0xffffffffu, lsum[mt][1], 2);
    }
    const int g = lane >> 2, tg = lane & 3;
    #pragma unroll
    for (int mt = 0; mt < 2; mt++) {
        const float inv0 = 1.0f / lsum[mt][0], inv1 = 1.0f / lsum[mt][1];
        const int r0 = q0 + wid * 32 + mt * 16 + g;
        #pragma unroll
        for (int nt = 0; nt < 8; nt++) {
            const int col = nt * 8 + tg * 2;
            size_t i0 = hoff + (size_t)r0 * DM + col;
            size_t i1 = i0 + (size_t)8 * DM;
            *(uint32_t*)&Ch[i0] = packf2h(o[mt][nt][0] * inv0, o[mt][nt][1] * inv0);
            *(uint32_t*)&Ch[i1] = packf2h(o[mt][nt][2] * inv1, o[mt][nt][3] * inv1);
        }
    }
}

// ---------------------------------------------------------------------------
extern "C" void kernel_launch(void* const* d_in, const int* in_sizes, int n_in,
                              void* d_out, int out_size)
{
    const float* X  = (const float*)d_in[0];
    const float* Wq = (const float*)d_in[1];
    const float* bq = (const float*)d_in[2];
    const float* Wk = (const float*)d_in[3];
    const float* bk = (const float*)d_in[4];
    const float* Wv = (const float*)d_in[5];
    const float* bv = (const float*)d_in[6];
    const float* Wo = (const float*)d_in[7];
    const float* bo = (const float*)d_in[8];
    float* out = (float*)d_out;

    __half *X16, *Q16, *K16, *V16, *C16;
    __half *Wq16, *Wk16, *Wv16, *Wo16;
    cudaGetSymbolAddress((void**)&X16, g_X16);
    cudaGetSymbolAddress((void**)&Q16, g_Q16);
    cudaGetSymbolAddress((void**)&K16, g_K16);
    cudaGetSymbolAddress((void**)&V16, g_V16);
    cudaGetSymbolAddress((void**)&C16, g_C16);
    cudaGetSymbolAddress((void**)&Wq16, g_Wq16);
    cudaGetSymbolAddress((void**)&Wk16, g_Wk16);
    cudaGetSymbolAddress((void**)&Wv16, g_Wv16);
    cudaGetSymbolAddress((void**)&Wo16, g_Wo16);

    cudaFuncSetAttribute(gemm_qkv, cudaFuncAttributeMaxDynamicSharedMemorySize, GEMM_SMEM);
    cudaFuncSetAttribute(gemm_o,   cudaFuncAttributeMaxDynamicSharedMemorySize, GEMM_SMEM);
    cudaFuncSetAttribute(attn_mma, cudaFuncAttributeMaxDynamicSharedMemorySize, ATT_SMEM);

    const int nX4 = MTOT * DM / 4, nW4 = DM * DM / 4;
    cvt_kernel<<<(nX4 + 255) / 256, 256>>>(X, X16, nX4);
    dim3 gw((nW4 + 255) / 256, 4);
    cvt4_kernel<<<gw, 256>>>(Wq, Wk, Wv, Wo, Wq16, Wk16, Wv16, Wo16, nW4);

    dim3 gqkv(DM / 128, MTOT / 128, 3);   // (8, 64, 3)
    gemm_qkv<<<gqkv, 128, GEMM_SMEM>>>(X16, Wq16, Wk16, Wv16, bq, bk, bv, Q16, K16, V16);

    dim3 ga(SEQ / ABQ, NH, BATCH);        // (16, 16, 4)
    attn_mma<<<ga, ATHR, ATT_SMEM>>>(Q16, K16, V16, C16);

    dim3 gg(DM / 128, MTOT / 128);        // (8, 64)
    gemm_o<<<gg, 128, GEMM_SMEM>>>(C16, Wo16, bo, out);
}

// round 10
// speedup vs baseline: 1.3855x; 1.3855x over previous
#include <cuda_runtime.h>
#include <cuda_fp16.h>
#include <cstdint>

#define BATCH 4
#define SEQ   2048
#define DM    1024
#define NH    16
#define DK    64
#define MTOT  (BATCH*SEQ)   // 8192

// ---------------- device scratch (allocation-free) ----------------
__device__ __half g_X16[MTOT*DM];
__device__ __half g_Q16[MTOT*DM], g_K16[MTOT*DM], g_V16[MTOT*DM];
__device__ __half g_C16[MTOT*DM];
__device__ __half g_Wq16[DM*DM], g_Wk16[DM*DM], g_Wv16[DM*DM], g_Wo16[DM*DM];

// ---------------- PTX helpers --------------------------------------------
__device__ __forceinline__ uint32_t smem_u32(const void* p) {
    uint32_t a;
    asm("{ .reg .u64 t; cvta.to.shared.u64 t, %1; cvt.u32.u64 %0, t; }" : "=r"(a) : "l"(p));
    return a;
}
__device__ __forceinline__ void cp16(uint32_t s, const void* g) {
    asm volatile("cp.async.cg.shared.global [%0], [%1], 16;" :: "r"(s), "l"(g));
}
__device__ __forceinline__ void cp_commit() {
    asm volatile("cp.async.commit_group;" ::: "memory");
}
template<int N> __device__ __forceinline__ void cp_wait() {
    asm volatile("cp.async.wait_group %0;" :: "n"(N) : "memory");
}
__device__ __forceinline__ void ldsm4(uint32_t& r0, uint32_t& r1, uint32_t& r2, uint32_t& r3,
                                      uint32_t addr) {
    asm volatile("ldmatrix.sync.aligned.m8n8.x4.shared.b16 {%0,%1,%2,%3}, [%4];"
                 : "=r"(r0), "=r"(r1), "=r"(r2), "=r"(r3) : "r"(addr));
}
__device__ __forceinline__ void ldsm4t(uint32_t& r0, uint32_t& r1, uint32_t& r2, uint32_t& r3,
                                       uint32_t addr) {
    asm volatile("ldmatrix.sync.aligned.m8n8.x4.trans.shared.b16 {%0,%1,%2,%3}, [%4];"
                 : "=r"(r0), "=r"(r1), "=r"(r2), "=r"(r3) : "r"(addr));
}
__device__ __forceinline__ void mma16816h(float* c, const uint32_t* a, const uint32_t* b) {
    asm volatile(
        "mma.sync.aligned.m16n8k16.row.col.f32.f16.f16.f32 "
        "{%0,%1,%2,%3}, {%4,%5,%6,%7}, {%8,%9}, {%0,%1,%2,%3};"
        : "+f"(c[0]), "+f"(c[1]), "+f"(c[2]), "+f"(c[3])
        : "r"(a[0]), "r"(a[1]), "r"(a[2]), "r"(a[3]), "r"(b[0]), "r"(b[1]));
}
__device__ __forceinline__ float ex2f(float x) {
    float y;
    asm("ex2.approx.ftz.f32 %0, %1;" : "=f"(y) : "f"(x));
    return y;
}
__device__ __forceinline__ uint32_t packf2h(float x, float y) {
    __half2 t = __floats2half2_rn(x, y);
    return *reinterpret_cast<uint32_t*>(&t);
}

// ---------------------------------------------------------------------------
// fp32 -> fp16 converters
// ---------------------------------------------------------------------------
__global__ void cvt_kernel(const float* __restrict__ in, __half* __restrict__ out, int n4)
{
    int i = blockIdx.x * blockDim.x + threadIdx.x;
    if (i >= n4) return;
    float4 v = ((const float4*)in)[i];
    uint32_t* op = reinterpret_cast<uint32_t*>(out) + 2 * i;
    op[0] = packf2h(v.x, v.y);
    op[1] = packf2h(v.z, v.w);
}
__global__ void cvt4_kernel(const float* __restrict__ a, const float* __restrict__ b,
                            const float* __restrict__ c, const float* __restrict__ d,
                            __half* oa, __half* ob, __half* oc, __half* od, int n4)
{
    int i = blockIdx.x * blockDim.x + threadIdx.x;
    if (i >= n4) return;
    const float* in = (blockIdx.y == 0) ? a : (blockIdx.y == 1) ? b : (blockIdx.y == 2) ? c : d;
    __half*     out = (blockIdx.y == 0) ? oa : (blockIdx.y == 1) ? ob : (blockIdx.y == 2) ? oc : od;
    float4 v = ((const float4*)in)[i];
    uint32_t* op = reinterpret_cast<uint32_t*>(out) + 2 * i;
    op[0] = packf2h(v.x, v.y);
    op[1] = packf2h(v.z, v.w);
}

// ---------------------------------------------------------------------------
// 1-pass fp16 GEMM:  C[8192,1024] = A @ W^T + bias  (optionally *scale)
// CTA 128x128, 128 threads = 4 warps, warp tile 64x64. KC=32 double-buffered.
// (unchanged from R8 — measured good)
// ---------------------------------------------------------------------------
#define KC        32
#define CHUNKS    (DM / KC)       // 32
#define ROWB      80              // smem bytes per 32-half row (+16B pad)
#define BUFB      (128 * ROWB)    // 10240
#define STGB      (2 * BUFB)      // 20480: A, B
#define GEMM_SMEM (2 * STGB)      // 40960

// EPI: 0 = fp32 out, 1 = fp16 out with scale
template<int EPI>
__device__ __forceinline__ void gemm_body(
    const __half* __restrict__ A_, const __half* __restrict__ B_,
    const float* __restrict__ bias, float scale,
    float* __restrict__ C, __half* __restrict__ Ch, char* smem)
{
    const uint32_t sbase = smem_u32(smem);
    const int tid = threadIdx.x, wid = tid >> 5, lane = tid & 31;
    const int bm = blockIdx.y * 128, bn = blockIdx.x * 128;
    const int wm = (wid & 1) * 64;     // warp m offset
    const int wn = (wid >> 1) * 64;    // warp n offset

    const char* pA = (const char*)(A_ + (size_t)bm * DM);
    const char* pB = (const char*)(B_ + (size_t)bn * DM);

    int so_[4]; size_t go_[4];
    #pragma unroll
    for (int j = 0; j < 4; j++) {
        int idx = j * 128 + tid;          // 0..511
        int row = idx >> 2, c16 = (idx & 3) * 16;
        so_[j] = row * ROWB + c16;
        go_[j] = (size_t)row * (DM * 2) + c16;
    }

    auto load_chunk = [&](int c) {
        uint32_t sb = sbase + (uint32_t)(c & 1) * STGB;
        size_t kb = (size_t)c * (KC * 2);
        #pragma unroll
        for (int j = 0; j < 4; j++) {
            size_t g = go_[j] + kb;
            cp16(sb + so_[j],        pA + g);
            cp16(sb + BUFB + so_[j], pB + g);
        }
        cp_commit();
    };

    float acc[4][8][4];
    #pragma unroll
    for (int mt = 0; mt < 4; mt++)
        #pragma unroll
        for (int nt = 0; nt < 8; nt++)
            #pragma unroll
            for (int e = 0; e < 4; e++) acc[mt][nt][e] = 0.0f;

    const int aRow = wm + (lane & 15);
    const int aKo  = (lane >> 4) * 16;
    const int bRow = wn + ((lane >> 4) & 1) * 8 + (lane & 7);
    const int bKo  = ((lane >> 3) & 1) * 16;

    load_chunk(0);
    load_chunk(1);

    for (int i = 0; i < CHUNKS; i++) {
        if (i == CHUNKS - 1) cp_wait<0>(); else cp_wait<1>();
        __syncthreads();

        const uint32_t sb = sbase + (uint32_t)(i & 1) * STGB;
        const uint32_t aB = sb, bB = sb + BUFB;

        #pragma unroll
        for (int ks = 0; ks < 2; ks++) {
            const int ko = ks * 32;
            uint32_t ah[4][4], bh[8][2];
            #pragma unroll
            for (int mt = 0; mt < 4; mt++)
                ldsm4(ah[mt][0], ah[mt][1], ah[mt][2], ah[mt][3],
                      aB + (uint32_t)((aRow + mt * 16) * ROWB + ko + aKo));
            #pragma unroll
            for (int np = 0; np < 4; np++)
                ldsm4(bh[2*np][0], bh[2*np][1], bh[2*np+1][0], bh[2*np+1][1],
                      bB + (uint32_t)((bRow + np * 16) * ROWB + ko + bKo));
            #pragma unroll
            for (int mt = 0; mt < 4; mt++)
                #pragma unroll
                for (int nt = 0; nt < 8; nt++)
                    mma16816h(acc[mt][nt], ah[mt], bh[nt]);
        }
        __syncthreads();
        if (i + 2 < CHUNKS) load_chunk(i + 2);
    }

    const int g  = lane >> 2, tg = lane & 3;
    #pragma unroll
    for (int mt = 0; mt < 4; mt++) {
        const int r0 = bm + wm + mt * 16 + g;
        #pragma unroll
        for (int nt = 0; nt < 8; nt++) {
            const int col = bn + wn + nt * 8 + tg * 2;
            const float b0 = bias[col], b1 = bias[col + 1];
            float v00 = acc[mt][nt][0] + b0, v01 = acc[mt][nt][1] + b1;
            float v10 = acc[mt][nt][2] + b0, v11 = acc[mt][nt][3] + b1;
            if (EPI == 0) {
                *(float2*)&C[(size_t)r0 * DM + col]       = make_float2(v00, v01);
                *(float2*)&C[(size_t)(r0 + 8) * DM + col] = make_float2(v10, v11);
            } else {
                *(uint32_t*)&Ch[(size_t)r0 * DM + col]       = packf2h(v00 * scale, v01 * scale);
                *(uint32_t*)&Ch[(size_t)(r0 + 8) * DM + col] = packf2h(v10 * scale, v11 * scale);
            }
        }
    }
}

#define SC2F (0.125f * 1.44269504088896f)   // 1/sqrt(dk) * log2(e)

__global__ __launch_bounds__(128)
void gemm_qkv(const __half* __restrict__ X16,
              const __half* __restrict__ Wq, const __half* __restrict__ Wk,
              const __half* __restrict__ Wv,
              const float* __restrict__ bq, const float* __restrict__ bk,
              const float* __restrict__ bv,
              __half* __restrict__ Q, __half* __restrict__ K, __half* __restrict__ V)
{
    extern __shared__ char smem[];
    const int z = blockIdx.z;
    const __half* W   = (z == 0) ? Wq : (z == 1) ? Wk : Wv;
    const float* bias = (z == 0) ? bq : (z == 1) ? bk : bv;
    __half* O         = (z == 0) ? Q  : (z == 1) ? K  : V;
    const float scale = (z == 0) ? SC2F : 1.0f;
    gemm_body<1>(X16, W, bias, scale, nullptr, O, smem);
}

__global__ __launch_bounds__(128)
void gemm_o(const __half* __restrict__ C16, const __half* __restrict__ Wo,
            const float* __restrict__ bo, float* __restrict__ out)
{
    extern __shared__ char smem[];
    gemm_body<0>(C16, Wo, bo, 1.0f, out, nullptr, smem);
}

// ---------------------------------------------------------------------------
// Tensor-core flash attention, fp16, static softmax (R7 shape: 8 warps, m=16).
// Softmax normalizer computed by an extra all-ones MMA column (no FADDs, no
// end-of-kernel shuffle reductions).
// ---------------------------------------------------------------------------
#define ABQ    128
#define ABKV   64
#define AROWB  144                 // 64 halves = 128B + 16B pad
#define AQSZ   (ABQ * AROWB)       // 18432
#define AKSZ   (ABKV * AROWB)      // 9216
#define ASTG   (2 * AKSZ)          // 18432: K, V
#define AKOFF  AQSZ
#define ATT_SMEM (AKOFF + 2 * ASTG)  // 55296
#define NKV    (SEQ / ABKV)        // 32

__global__ __launch_bounds__(256, 3)
void attn_mma(const __half* __restrict__ Qg, const __half* __restrict__ Kg,
              const __half* __restrict__ Vg, __half* __restrict__ Ch)
{
    extern __shared__ char smem[];
    const uint32_t sbase = smem_u32(smem);
    const int b   = blockIdx.z;
    const int h   = blockIdx.y;
    const int q0  = blockIdx.x * ABQ;
    const int tid = threadIdx.x, wid = tid >> 5, lane = tid & 31;

    const size_t hoff = ((size_t)b * SEQ) * DM + (size_t)h * DK;
    const char* gQ = (const char*)(Qg + hoff + (size_t)q0 * DM);
    const char* gK = (const char*)(Kg + hoff);
    const char* gV = (const char*)(Vg + hoff);

    // ---- load Q tile ----
    #pragma unroll
    for (int j = 0; j < 4; j++) {
        int idx = tid + j * 256;          // 0..1023
        int row = idx >> 3, seg = (idx & 7) * 16;
        cp16(sbase + (uint32_t)(row * AROWB + seg), gQ + (size_t)row * (DM * 2) + seg);
    }
    cp_commit();

    // ---- kv tile loader ----
    int so_[2]; size_t go_[2];
    #pragma unroll
    for (int j = 0; j < 2; j++) {
        int idx = tid + j * 256;          // 0..511
        int row = idx >> 3, seg = (idx & 7) * 16;
        so_[j] = row * AROWB + seg;
        go_[j] = (size_t)row * (DM * 2) + seg;
    }
    auto load_kv = [&](int it) {
        uint32_t sb = sbase + AKOFF + (uint32_t)(it & 1) * ASTG;
        size_t kvb = (size_t)it * ABKV * (DM * 2);
        #pragma unroll
        for (int j = 0; j < 2; j++) {
            size_t g = go_[j] + kvb;
            cp16(sb + so_[j],        gK + g);
            cp16(sb + AKSZ + so_[j], gV + g);
        }
        cp_commit();
    };
    load_kv(0);
    load_kv(1);

    // ---- Q fragments to registers ----
    cp_wait<2>();
    __syncthreads();
    uint32_t qh[4][4];
    {
        const int qrow = wid * 16 + (lane & 15);
        const int qko  = (lane >> 4) * 16;
        #pragma unroll
        for (int j = 0; j < 4; j++)
            ldsm4(qh[j][0], qh[j][1], qh[j][2], qh[j][3],
                  sbase + (uint32_t)(qrow * AROWB + j * 32 + qko));
    }

    float o[8][4];
    #pragma unroll
    for (int nt = 0; nt < 8; nt++)
        #pragma unroll
        for (int e = 0; e < 4; e++) o[nt][e] = 0.0f;
    float lacc[4] = {0.0f, 0.0f, 0.0f, 0.0f};          // rowsum accumulator (ones-MMA)
    const uint32_t ones2 = 0x3C003C00u;                // (1.0h, 1.0h)
    uint32_t onesb[2] = {ones2, ones2};

    const int kRow = ((lane >> 4) & 1) * 8 + (lane & 7);
    const int kKo  = ((lane >> 3) & 1) * 16;
    const int vRow = ((lane >> 3) & 1) * 8 + (lane & 7);
    const int vCo  = ((lane >> 4) & 1) * 16;

    for (int it = 0; it < NKV; it++) {
        if (it == NKV - 1) cp_wait<0>(); else cp_wait<1>();
        __syncthreads();
        const uint32_t sb = sbase + AKOFF + (uint32_t)(it & 1) * ASTG;

        // ---- S = Q.K^T (1-pass fp16; Q pre-scaled, so s is a base-2 logit) ----
        float s[8][4];
        #pragma unroll
        for (int nt = 0; nt < 8; nt++)
            #pragma unroll
            for (int e = 0; e < 4; e++) s[nt][e] = 0.0f;
        #pragma unroll
        for (int j = 0; j < 4; j++) {
            uint32_t kf[8][2];
            #pragma unroll
            for (int np = 0; np < 4; np++)
                ldsm4(kf[2*np][0], kf[2*np][1], kf[2*np+1][0], kf[2*np+1][1],
                      sb + (uint32_t)((np * 16 + kRow) * AROWB + j * 32 + kKo));
            #pragma unroll
            for (int nt = 0; nt < 8; nt++) mma16816h(s[nt], qh[j], kf[nt]);
        }

        // ---- static softmax: P = exp2(s), pack to fp16 A-frags ----
        uint32_t ph[4][4];
        #pragma unroll
        for (int j = 0; j < 4; j++) {
            const int t0 = 2 * j, t1 = 2 * j + 1;
            float p00 = ex2f(s[t0][0]), p01 = ex2f(s[t0][1]);
            float p02 = ex2f(s[t0][2]), p03 = ex2f(s[t0][3]);
            float p10 = ex2f(s[t1][0]), p11 = ex2f(s[t1][1]);
            float p12 = ex2f(s[t1][2]), p13 = ex2f(s[t1][3]);
            ph[j][0] = packf2h(p00, p01);
            ph[j][1] = packf2h(p02, p03);
            ph[j][2] = packf2h(p10, p11);
            ph[j][3] = packf2h(p12, p13);
        }

        // ---- O += P.V (1-pass) + rowsum via ones-column MMA ----
        #pragma unroll
        for (int j = 0; j < 4; j++) {
            uint32_t vf[8][2];
            #pragma unroll
            for (int np = 0; np < 4; np++)
                ldsm4t(vf[2*np][0], vf[2*np][1], vf[2*np+1][0], vf[2*np+1][1],
                       sb + AKSZ + (uint32_t)((16 * j + vRow) * AROWB + np * 32 + vCo));
            #pragma unroll
            for (int nt = 0; nt < 8; nt++) mma16816h(o[nt], ph[j], vf[nt]);
            mma16816h(lacc, ph[j], onesb);   // l[row] += sum_k P[row][k]
        }

        __syncthreads();
        if (it + 2 < NKV) load_kv(it + 2);
    }

    // ---- normalize (rowsum already per-thread in lacc), store ----
    const float inv0 = 1.0f / lacc[0], inv1 = 1.0f / lacc[2];
    const int g = lane >> 2, tg = lane & 3;
    const int r0 = q0 + wid * 16 + g;
    #pragma unroll
    for (int nt = 0; nt < 8; nt++) {
        const int col = nt * 8 + tg * 2;
        size_t i0 = hoff + (size_t)r0 * DM + col;
        size_t i1 = i0 + (size_t)8 * DM;
        *(uint32_t*)&Ch[i0] = packf2h(o[nt][0] * inv0, o[nt][1] * inv0);
        *(uint32_t*)&Ch[i1] = packf2h(o[nt][2] * inv1, o[nt][3] * inv1);
    }
}

// ---------------------------------------------------------------------------
extern "C" void kernel_launch(void* const* d_in, const int* in_sizes, int n_in,
                              void* d_out, int out_size)
{
    const float* X  = (const float*)d_in[0];
    const float* Wq = (const float*)d_in[1];
    const float* bq = (const float*)d_in[2];
    const float* Wk = (const float*)d_in[3];
    const float* bk = (const float*)d_in[4];
    const float* Wv = (const float*)d_in[5];
    const float* bv = (const float*)d_in[6];
    const float* Wo = (const float*)d_in[7];
    const float* bo = (const float*)d_in[8];
    float* out = (float*)d_out;

    __half *X16, *Q16, *K16, *V16, *C16;
    __half *Wq16, *Wk16, *Wv16, *Wo16;
    cudaGetSymbolAddress((void**)&X16, g_X16);
    cudaGetSymbolAddress((void**)&Q16, g_Q16);
    cudaGetSymbolAddress((void**)&K16, g_K16);
    cudaGetSymbolAddress((void**)&V16, g_V16);
    cudaGetSymbolAddress((void**)&C16, g_C16);
    cudaGetSymbolAddress((void**)&Wq16, g_Wq16);
    cudaGetSymbolAddress((void**)&Wk16, g_Wk16);
    cudaGetSymbolAddress((void**)&Wv16, g_Wv16);
    cudaGetSymbolAddress((void**)&Wo16, g_Wo16);

    cudaFuncSetAttribute(gemm_qkv, cudaFuncAttributeMaxDynamicSharedMemorySize, GEMM_SMEM);
    cudaFuncSetAttribute(gemm_o,   cudaFuncAttributeMaxDynamicSharedMemorySize, GEMM_SMEM);
    cudaFuncSetAttribute(attn_mma, cudaFuncAttributeMaxDynamicSharedMemorySize, ATT_SMEM);

    const int nX4 = MTOT * DM / 4, nW4 = DM * DM / 4;
    cvt_kernel<<<(nX4 + 255) / 256, 256>>>(X, X16, nX4);
    dim3 gw((nW4 + 255) / 256, 4);
    cvt4_kernel<<<gw, 256>>>(Wq, Wk, Wv, Wo, Wq16, Wk16, Wv16, Wo16, nW4);

    dim3 gqkv(DM / 128, MTOT / 128, 3);   // (8, 64, 3)
    gemm_qkv<<<gqkv, 128, GEMM_SMEM>>>(X16, Wq16, Wk16, Wv16, bq, bk, bv, Q16, K16, V16);

    dim3 ga(SEQ / ABQ, NH, BATCH);        // (16, 16, 4)
    attn_mma<<<ga, 256, ATT_SMEM>>>(Q16, K16, V16, C16);

    dim3 gg(DM / 128, MTOT / 128);        // (8, 64)
    gemm_o<<<gg, 128, GEMM_SMEM>>>(C16, Wo16, bo, out);
}

// round 12
// speedup vs baseline: 1.4625x; 1.0556x over previous
#include <cuda_runtime.h>
#include <cuda_fp16.h>
#include <cstdint>

#define BATCH 4
#define SEQ   2048
#define DM    1024
#define NH    16
#define DK    64
#define MTOT  (BATCH*SEQ)   // 8192

// ---------------- device scratch (allocation-free) ----------------
__device__ __half g_X16[MTOT*DM];
__device__ __half g_Q16[MTOT*DM], g_K16[MTOT*DM], g_V16[MTOT*DM];
__device__ __half g_C16[MTOT*DM];
__device__ __half g_Wq16[DM*DM], g_Wk16[DM*DM], g_Wv16[DM*DM], g_Wo16[DM*DM];

// ---------------- PTX helpers --------------------------------------------
__device__ __forceinline__ uint32_t smem_u32(const void* p) {
    uint32_t a;
    asm("{ .reg .u64 t; cvta.to.shared.u64 t, %1; cvt.u32.u64 %0, t; }" : "=r"(a) : "l"(p));
    return a;
}
__device__ __forceinline__ void cp16(uint32_t s, const void* g) {
    asm volatile("cp.async.cg.shared.global [%0], [%1], 16;" :: "r"(s), "l"(g));
}
__device__ __forceinline__ void cp_commit() {
    asm volatile("cp.async.commit_group;" ::: "memory");
}
template<int N> __device__ __forceinline__ void cp_wait() {
    asm volatile("cp.async.wait_group %0;" :: "n"(N) : "memory");
}
__device__ __forceinline__ void ldsm4(uint32_t& r0, uint32_t& r1, uint32_t& r2, uint32_t& r3,
                                      uint32_t addr) {
    asm volatile("ldmatrix.sync.aligned.m8n8.x4.shared.b16 {%0,%1,%2,%3}, [%4];"
                 : "=r"(r0), "=r"(r1), "=r"(r2), "=r"(r3) : "r"(addr));
}
__device__ __forceinline__ void ldsm4t(uint32_t& r0, uint32_t& r1, uint32_t& r2, uint32_t& r3,
                                       uint32_t addr) {
    asm volatile("ldmatrix.sync.aligned.m8n8.x4.trans.shared.b16 {%0,%1,%2,%3}, [%4];"
                 : "=r"(r0), "=r"(r1), "=r"(r2), "=r"(r3) : "r"(addr));
}
__device__ __forceinline__ void mma16816h(float* c, const uint32_t* a, const uint32_t* b) {
    asm volatile(
        "mma.sync.aligned.m16n8k16.row.col.f32.f16.f16.f32 "
        "{%0,%1,%2,%3}, {%4,%5,%6,%7}, {%8,%9}, {%0,%1,%2,%3};"
        : "+f"(c[0]), "+f"(c[1]), "+f"(c[2]), "+f"(c[3])
        : "r"(a[0]), "r"(a[1]), "r"(a[2]), "r"(a[3]), "r"(b[0]), "r"(b[1]));
}
__device__ __forceinline__ float ex2f(float x) {
    float y;
    asm("ex2.approx.ftz.f32 %0, %1;" : "=f"(y) : "f"(x));
    return y;
}
__device__ __forceinline__ uint32_t packf2h(float x, float y) {
    __half2 t = __floats2half2_rn(x, y);
    return *reinterpret_cast<uint32_t*>(&t);
}

// ---------------------------------------------------------------------------
// fp32 -> fp16 converters
// ---------------------------------------------------------------------------
__global__ void cvt_kernel(const float* __restrict__ in, __half* __restrict__ out, int n4)
{
    int i = blockIdx.x * blockDim.x + threadIdx.x;
    if (i >= n4) return;
    float4 v = ((const float4*)in)[i];
    uint32_t* op = reinterpret_cast<uint32_t*>(out) + 2 * i;
    op[0] = packf2h(v.x, v.y);
    op[1] = packf2h(v.z, v.w);
}
__global__ void cvt4_kernel(const float* __restrict__ a, const float* __restrict__ b,
                            const float* __restrict__ c, const float* __restrict__ d,
                            __half* oa, __half* ob, __half* oc, __half* od, int n4)
{
    int i = blockIdx.x * blockDim.x + threadIdx.x;
    if (i >= n4) return;
    const float* in = (blockIdx.y == 0) ? a : (blockIdx.y == 1) ? b : (blockIdx.y == 2) ? c : d;
    __half*     out = (blockIdx.y == 0) ? oa : (blockIdx.y == 1) ? ob : (blockIdx.y == 2) ? oc : od;
    float4 v = ((const float4*)in)[i];
    uint32_t* op = reinterpret_cast<uint32_t*>(out) + 2 * i;
    op[0] = packf2h(v.x, v.y);
    op[1] = packf2h(v.z, v.w);
}

// ---------------------------------------------------------------------------
// 1-pass fp16 GEMM:  C[8192,1024] = A @ W^T + bias  (optionally *scale)
// CTA 128x128, 128 threads = 4 warps, warp tile 64x64. KC=32 double-buffered.
// (R8 shape — measured best)
// ---------------------------------------------------------------------------
#define KC        32
#define CHUNKS    (DM / KC)       // 32
#define ROWB      80              // smem bytes per 32-half row (+16B pad)
#define BUFB      (128 * ROWB)    // 10240
#define STGB      (2 * BUFB)      // 20480: A, B
#define GEMM_SMEM (2 * STGB)      // 40960

// EPI: 0 = fp32 out, 1 = fp16 out with scale
template<int EPI>
__device__ __forceinline__ void gemm_body(
    const __half* __restrict__ A_, const __half* __restrict__ B_,
    const float* __restrict__ bias, float scale,
    float* __restrict__ C, __half* __restrict__ Ch, char* smem)
{
    const uint32_t sbase = smem_u32(smem);
    const int tid = threadIdx.x, wid = tid >> 5, lane = tid & 31;
    const int bm = blockIdx.y * 128, bn = blockIdx.x * 128;
    const int wm = (wid & 1) * 64;     // warp m offset
    const int wn = (wid >> 1) * 64;    // warp n offset

    const char* pA = (const char*)(A_ + (size_t)bm * DM);
    const char* pB = (const char*)(B_ + (size_t)bn * DM);

    int so_[4]; size_t go_[4];
    #pragma unroll
    for (int j = 0; j < 4; j++) {
        int idx = j * 128 + tid;          // 0..511
        int row = idx >> 2, c16 = (idx & 3) * 16;
        so_[j] = row * ROWB + c16;
        go_[j] = (size_t)row * (DM * 2) + c16;
    }

    auto load_chunk = [&](int c) {
        uint32_t sb = sbase + (uint32_t)(c & 1) * STGB;
        size_t kb = (size_t)c * (KC * 2);
        #pragma unroll
        for (int j = 0; j < 4; j++) {
            size_t g = go_[j] + kb;
            cp16(sb + so_[j],        pA + g);
            cp16(sb + BUFB + so_[j], pB + g);
        }
        cp_commit();
    };

    float acc[4][8][4];
    #pragma unroll
    for (int mt = 0; mt < 4; mt++)
        #pragma unroll
        for (int nt = 0; nt < 8; nt++)
            #pragma unroll
            for (int e = 0; e < 4; e++) acc[mt][nt][e] = 0.0f;

    const int aRow = wm + (lane & 15);
    const int aKo  = (lane >> 4) * 16;
    const int bRow = wn + ((lane >> 4) & 1) * 8 + (lane & 7);
    const int bKo  = ((lane >> 3) & 1) * 16;

    load_chunk(0);
    load_chunk(1);

    for (int i = 0; i < CHUNKS; i++) {
        if (i == CHUNKS - 1) cp_wait<0>(); else cp_wait<1>();
        __syncthreads();

        const uint32_t sb = sbase + (uint32_t)(i & 1) * STGB;
        const uint32_t aB = sb, bB = sb + BUFB;

        #pragma unroll
        for (int ks = 0; ks < 2; ks++) {
            const int ko = ks * 32;
            uint32_t ah[4][4], bh[8][2];
            #pragma unroll
            for (int mt = 0; mt < 4; mt++)
                ldsm4(ah[mt][0], ah[mt][1], ah[mt][2], ah[mt][3],
                      aB + (uint32_t)((aRow + mt * 16) * ROWB + ko + aKo));
            #pragma unroll
            for (int np = 0; np < 4; np++)
                ldsm4(bh[2*np][0], bh[2*np][1], bh[2*np+1][0], bh[2*np+1][1],
                      bB + (uint32_t)((bRow + np * 16) * ROWB + ko + bKo));
            #pragma unroll
            for (int mt = 0; mt < 4; mt++)
                #pragma unroll
                for (int nt = 0; nt < 8; nt++)
                    mma16816h(acc[mt][nt], ah[mt], bh[nt]);
        }
        __syncthreads();
        if (i + 2 < CHUNKS) load_chunk(i + 2);
    }

    const int g  = lane >> 2, tg = lane & 3;
    #pragma unroll
    for (int mt = 0; mt < 4; mt++) {
        const int r0 = bm + wm + mt * 16 + g;
        #pragma unroll
        for (int nt = 0; nt < 8; nt++) {
            const int col = bn + wn + nt * 8 + tg * 2;
            const float b0 = bias[col], b1 = bias[col + 1];
            float v00 = acc[mt][nt][0] + b0, v01 = acc[mt][nt][1] + b1;
            float v10 = acc[mt][nt][2] + b0, v11 = acc[mt][nt][3] + b1;
            if (EPI == 0) {
                *(float2*)&C[(size_t)r0 * DM + col]       = make_float2(v00, v01);
                *(float2*)&C[(size_t)(r0 + 8) * DM + col] = make_float2(v10, v11);
            } else {
                *(uint32_t*)&Ch[(size_t)r0 * DM + col]       = packf2h(v00 * scale, v01 * scale);
                *(uint32_t*)&Ch[(size_t)(r0 + 8) * DM + col] = packf2h(v10 * scale, v11 * scale);
            }
        }
    }
}

#define SC2F (0.125f * 1.44269504088896f)   // 1/sqrt(dk) * log2(e)

__global__ __launch_bounds__(128)
void gemm_qkv(const __half* __restrict__ X16,
              const __half* __restrict__ Wq, const __half* __restrict__ Wk,
              const __half* __restrict__ Wv,
              const float* __restrict__ bq, const float* __restrict__ bk,
              const float* __restrict__ bv,
              __half* __restrict__ Q, __half* __restrict__ K, __half* __restrict__ V)
{
    extern __shared__ char smem[];
    const int z = blockIdx.z;
    const __half* W   = (z == 0) ? Wq : (z == 1) ? Wk : Wv;
    const float* bias = (z == 0) ? bq : (z == 1) ? bk : bv;
    __half* O         = (z == 0) ? Q  : (z == 1) ? K  : V;
    const float scale = (z == 0) ? SC2F : 1.0f;
    gemm_body<1>(X16, W, bias, scale, nullptr, O, smem);
}

__global__ __launch_bounds__(128)
void gemm_o(const __half* __restrict__ C16, const __half* __restrict__ Wo,
            const float* __restrict__ bo, float* __restrict__ out)
{
    extern __shared__ char smem[];
    gemm_body<0>(C16, Wo, bo, 1.0f, out, nullptr, smem);
}

// ---------------------------------------------------------------------------
// Tensor-core flash attention, fp16, static softmax — EXACT R7 configuration
// (measured best: 182 us). 8 warps x m16, ABQ=128, FADD rowsum + end shuffles.
// ---------------------------------------------------------------------------
#define ABQ    128
#define ABKV   64
#define AROWB  144                 // 64 halves = 128B + 16B pad
#define AQSZ   (ABQ * AROWB)       // 18432
#define AKSZ   (ABKV * AROWB)      // 9216
#define ASTG   (2 * AKSZ)          // 18432: K, V
#define AKOFF  AQSZ
#define ATT_SMEM (AKOFF + 2 * ASTG)  // 55296
#define NKV    (SEQ / ABKV)        // 32

__global__ __launch_bounds__(256)
void attn_mma(const __half* __restrict__ Qg, const __half* __restrict__ Kg,
              const __half* __restrict__ Vg, __half* __restrict__ Ch)
{
    extern __shared__ char smem[];
    const uint32_t sbase = smem_u32(smem);
    const int b   = blockIdx.z;
    const int h   = blockIdx.y;
    const int q0  = blockIdx.x * ABQ;
    const int tid = threadIdx.x, wid = tid >> 5, lane = tid & 31;

    const size_t hoff = ((size_t)b * SEQ) * DM + (size_t)h * DK;
    const char* gQ = (const char*)(Qg + hoff + (size_t)q0 * DM);
    const char* gK = (const char*)(Kg + hoff);
    const char* gV = (const char*)(Vg + hoff);

    // ---- load Q tile ----
    #pragma unroll
    for (int j = 0; j < 4; j++) {
        int idx = tid + j * 256;          // 0..1023
        int row = idx >> 3, seg = (idx & 7) * 16;
        cp16(sbase + (uint32_t)(row * AROWB + seg), gQ + (size_t)row * (DM * 2) + seg);
    }
    cp_commit();

    // ---- kv tile loader ----
    int so_[2]; size_t go_[2];
    #pragma unroll
    for (int j = 0; j < 2; j++) {
        int idx = tid + j * 256;          // 0..511
        int row = idx >> 3, seg = (idx & 7) * 16;
        so_[j] = row * AROWB + seg;
        go_[j] = (size_t)row * (DM * 2) + seg;
    }
    auto load_kv = [&](int it) {
        uint32_t sb = sbase + AKOFF + (uint32_t)(it & 1) * ASTG;
        size_t kvb = (size_t)it * ABKV * (DM * 2);
        #pragma unroll
        for (int j = 0; j < 2; j++) {
            size_t g = go_[j] + kvb;
            cp16(sb + so_[j],        gK + g);
            cp16(sb + AKSZ + so_[j], gV + g);
        }
        cp_commit();
    };
    load_kv(0);
    load_kv(1);

    // ---- Q fragments to registers ----
    cp_wait<2>();
    __syncthreads();
    uint32_t qh[4][4];
    {
        const int qrow = wid * 16 + (lane & 15);
        const int qko  = (lane >> 4) * 16;
        #pragma unroll
        for (int j = 0; j < 4; j++)
            ldsm4(qh[j][0], qh[j][1], qh[j][2], qh[j][3],
                  sbase + (uint32_t)(qrow * AROWB + j * 32 + qko));
    }

    float o[8][4];
    #pragma unroll
    for (int nt = 0; nt < 8; nt++)
        #pragma unroll
        for (int e = 0; e < 4; e++) o[nt][e] = 0.0f;
    float lsum0 = 0.0f, lsum1 = 0.0f;

    const int kRow = ((lane >> 4) & 1) * 8 + (lane & 7);
    const int kKo  = ((lane >> 3) & 1) * 16;
    const int vRow = ((lane >> 3) & 1) * 8 + (lane & 7);
    const int vCo  = ((lane >> 4) & 1) * 16;

    for (int it = 0; it < NKV; it++) {
        if (it == NKV - 1) cp_wait<0>(); else cp_wait<1>();
        __syncthreads();
        const uint32_t sb = sbase + AKOFF + (uint32_t)(it & 1) * ASTG;

        // ---- S = Q.K^T (1-pass fp16; Q pre-scaled, so s is a base-2 logit) ----
        float s[8][4];
        #pragma unroll
        for (int nt = 0; nt < 8; nt++)
            #pragma unroll
            for (int e = 0; e < 4; e++) s[nt][e] = 0.0f;
        #pragma unroll
        for (int j = 0; j < 4; j++) {
            uint32_t kf[8][2];
            #pragma unroll
            for (int np = 0; np < 4; np++)
                ldsm4(kf[2*np][0], kf[2*np][1], kf[2*np+1][0], kf[2*np+1][1],
                      sb + (uint32_t)((np * 16 + kRow) * AROWB + j * 32 + kKo));
            #pragma unroll
            for (int nt = 0; nt < 8; nt++) mma16816h(s[nt], qh[j], kf[nt]);
        }

        // ---- static softmax: P = exp2(s), accumulate l, pack to fp16 frags ----
        uint32_t ph[4][4];
        #pragma unroll
        for (int j = 0; j < 4; j++) {
            const int t0 = 2 * j, t1 = 2 * j + 1;
            float p00 = ex2f(s[t0][0]), p01 = ex2f(s[t0][1]);
            float p02 = ex2f(s[t0][2]), p03 = ex2f(s[t0][3]);
            float p10 = ex2f(s[t1][0]), p11 = ex2f(s[t1][1]);
            float p12 = ex2f(s[t1][2]), p13 = ex2f(s[t1][3]);
            lsum0 += (p00 + p01) + (p10 + p11);
            lsum1 += (p02 + p03) + (p12 + p13);
            ph[j][0] = packf2h(p00, p01);
            ph[j][1] = packf2h(p02, p03);
            ph[j][2] = packf2h(p10, p11);
            ph[j][3] = packf2h(p12, p13);
        }

        // ---- O += P.V (1-pass) ----
        #pragma unroll
        for (int j = 0; j < 4; j++) {
            uint32_t vf[8][2];
            #pragma unroll
            for (int np = 0; np < 4; np++)
                ldsm4t(vf[2*np][0], vf[2*np][1], vf[2*np+1][0], vf[2*np+1][1],
                       sb + AKSZ + (uint32_t)((16 * j + vRow) * AROWB + np * 32 + vCo));
            #pragma unroll
            for (int nt = 0; nt < 8; nt++) mma16816h(o[nt], ph[j], vf[nt]);
        }

        __syncthreads();
        if (it + 2 < NKV) load_kv(it + 2);
    }

    // ---- final l reduction (within 4-lane row groups), normalize, store ----
    lsum0 += __shfl_xor_sync(0xffffffffu, lsum0, 1);
    lsum0 += __shfl_xor_sync(0xffffffffu, lsum0, 2);
    lsum1 += __shfl_xor_sync(0xffffffffu, lsum1, 1);
    lsum1 += __shfl_xor_sync(0xffffffffu, lsum1, 2);
    const float inv0 = 1.0f / lsum0, inv1 = 1.0f / lsum1;
    const int g = lane >> 2, tg = lane & 3;
    const int r0 = q0 + wid * 16 + g;
    #pragma unroll
    for (int nt = 0; nt < 8; nt++) {
        const int col = nt * 8 + tg * 2;
        size_t i0 = hoff + (size_t)r0 * DM + col;
        size_t i1 = i0 + (size_t)8 * DM;
        *(uint32_t*)&Ch[i0] = packf2h(o[nt][0] * inv0, o[nt][1] * inv0);
        *(uint32_t*)&Ch[i1] = packf2h(o[nt][2] * inv1, o[nt][3] * inv1);
    }
}

// ---------------------------------------------------------------------------
extern "C" void kernel_launch(void* const* d_in, const int* in_sizes, int n_in,
                              void* d_out, int out_size)
{
    const float* X  = (const float*)d_in[0];
    const float* Wq = (const float*)d_in[1];
    const float* bq = (const float*)d_in[2];
    const float* Wk = (const float*)d_in[3];
    const float* bk = (const float*)d_in[4];
    const float* Wv = (const float*)d_in[5];
    const float* bv = (const float*)d_in[6];
    const float* Wo = (const float*)d_in[7];
    const float* bo = (const float*)d_in[8];
    float* out = (float*)d_out;

    __half *X16, *Q16, *K16, *V16, *C16;
    __half *Wq16, *Wk16, *Wv16, *Wo16;
    cudaGetSymbolAddress((void**)&X16, g_X16);
    cudaGetSymbolAddress((void**)&Q16, g_Q16);
    cudaGetSymbolAddress((void**)&K16, g_K16);
    cudaGetSymbolAddress((void**)&V16, g_V16);
    cudaGetSymbolAddress((void**)&C16, g_C16);
    cudaGetSymbolAddress((void**)&Wq16, g_Wq16);
    cudaGetSymbolAddress((void**)&Wk16, g_Wk16);
    cudaGetSymbolAddress((void**)&Wv16, g_Wv16);
    cudaGetSymbolAddress((void**)&Wo16, g_Wo16);

    cudaFuncSetAttribute(gemm_qkv, cudaFuncAttributeMaxDynamicSharedMemorySize, GEMM_SMEM);
    cudaFuncSetAttribute(gemm_o,   cudaFuncAttributeMaxDynamicSharedMemorySize, GEMM_SMEM);
    cudaFuncSetAttribute(attn_mma, cudaFuncAttributeMaxDynamicSharedMemorySize, ATT_SMEM);

    const int nX4 = MTOT * DM / 4, nW4 = DM * DM / 4;
    cvt_kernel<<<(nX4 + 255) / 256, 256>>>(X, X16, nX4);
    dim3 gw((nW4 + 255) / 256, 4);
    cvt4_kernel<<<gw, 256>>>(Wq, Wk, Wv, Wo, Wq16, Wk16, Wv16, Wo16, nW4);

    dim3 gqkv(DM / 128, MTOT / 128, 3);   // (8, 64, 3)
    gemm_qkv<<<gqkv, 128, GEMM_SMEM>>>(X16, Wq16, Wk16, Wv16, bq, bk, bv, Q16, K16, V16);

    dim3 ga(SEQ / ABQ, NH, BATCH);        // (16, 16, 4)
    attn_mma<<<ga, 256, ATT_SMEM>>>(Q16, K16, V16, C16);

    dim3 gg(DM / 128, MTOT / 128);        // (8, 64)
    gemm_o<<<gg, 128, GEMM_SMEM>>>(C16, Wo16, bo, out);
}